// round 2
// baseline (speedup 1.0000x reference)
#include <cuda_runtime.h>
#include <cuda_bf16.h>
#include <math.h>

// ---------------------------------------------------------------------------
// Problem constants
//   N=2048, T=128, IN=64, H=256, 3H=768, NH=2, HD=128, C=30
// ---------------------------------------------------------------------------

#define NB    2048
#define TT    128
#define INDIM 64
#define HH    256
#define G3    768
#define NHD   2
#define HD    128
#define CC    30
#define NTROWS (NB * TT)   // 262144

// ---------------------------------------------------------------------------
// Device scratch (allocation-free rule: __device__ globals)
// ---------------------------------------------------------------------------
__device__ float g_xw[(size_t)NTROWS * G3];   // 805 MB: xW for current layer
__device__ float g_ys0[(size_t)NTROWS * HH];  // 268 MB: layer-0 outputs
__device__ float g_gates[NB * G3];            // per-step h @ Whh^T + bhh
__device__ float g_h[NB * HH];                // hidden state
__device__ float g_qh1[NHD * CC * HD];
__device__ float g_kh1[NHD * NB * HD];
__device__ float g_vh1[NHD * NB * HD];
__device__ float g_B[CC * NHD * HD];          // (30, 256)
__device__ float g_qh2[NHD * NB * HD];
__device__ float g_kh2[NHD * CC * HD];
__device__ float g_vh2[NHD * CC * HD];
__device__ float g_Sp[NB * HH];
__device__ float g_Smix[NB * HH];
__device__ float g_mlp[NB * HH];
__device__ float g_yraw[NB];

// ---------------------------------------------------------------------------
// Tiled GEMM: C[M,Nn] = A[M,K] @ W[Nn,K]^T + bias[Nn]
// Requires M%64==0, Nn%64==0, K%16==0. Block (16,16), 64x64 tile, BK=16,
// each thread computes a 4x4 fragment from transposed SMEM tiles (float4,
// conflict-free compute reads).
// ---------------------------------------------------------------------------
__global__ __launch_bounds__(256) void gemm_bias_kernel(
    const float* __restrict__ A, int lda,
    const float* __restrict__ W,
    const float* __restrict__ bias,
    float* __restrict__ C, int ldc,
    int M, int Nn, int K)
{
    __shared__ float As[16][64];
    __shared__ float Ws[16][64];
    const int tx = threadIdx.x, ty = threadIdx.y;
    const int tid = ty * 16 + tx;
    const int row0 = blockIdx.y * 64;
    const int col0 = blockIdx.x * 64;
    const int lm = tid >> 2;          // 0..63
    const int lk = (tid & 3) << 2;    // 0,4,8,12
    const float* Aptr = A + (size_t)(row0 + lm) * lda + lk;
    const float* Wptr = W + (size_t)(col0 + lm) * K + lk;

    float acc[4][4];
#pragma unroll
    for (int i = 0; i < 4; i++)
#pragma unroll
        for (int j = 0; j < 4; j++) acc[i][j] = 0.f;

    for (int k0 = 0; k0 < K; k0 += 16) {
        float4 av = *(const float4*)(Aptr + k0);
        float4 wv = *(const float4*)(Wptr + k0);
        As[lk + 0][lm] = av.x; As[lk + 1][lm] = av.y;
        As[lk + 2][lm] = av.z; As[lk + 3][lm] = av.w;
        Ws[lk + 0][lm] = wv.x; Ws[lk + 1][lm] = wv.y;
        Ws[lk + 2][lm] = wv.z; Ws[lk + 3][lm] = wv.w;
        __syncthreads();
#pragma unroll
        for (int k = 0; k < 16; k++) {
            float4 a = *(const float4*)(&As[k][ty << 2]);
            float4 b = *(const float4*)(&Ws[k][tx << 2]);
            float ar[4] = {a.x, a.y, a.z, a.w};
            float br[4] = {b.x, b.y, b.z, b.w};
#pragma unroll
            for (int i = 0; i < 4; i++)
#pragma unroll
                for (int j = 0; j < 4; j++) acc[i][j] += ar[i] * br[j];
        }
        __syncthreads();
    }
#pragma unroll
    for (int i = 0; i < 4; i++) {
        const int r = row0 + (ty << 2) + i;
        float* Crow = C + (size_t)r * ldc + col0 + (tx << 2);
#pragma unroll
        for (int j = 0; j < 4; j++)
            Crow[j] = acc[i][j] + bias[col0 + (tx << 2) + j];
    }
}

// ---------------------------------------------------------------------------
// GRU gate update: reads xW slice (row stride ldxw) + gates (h@Whh^T+bhh),
// updates h in place, optionally stores h to ys (layer-0 sequence buffer).
// ---------------------------------------------------------------------------
__global__ void gru_gate_kernel(const float* __restrict__ xw, size_t ldxw,
                                const float* __restrict__ g,
                                float* __restrict__ h,
                                float* __restrict__ ys, size_t ldys)
{
    const int idx = blockIdx.x * blockDim.x + threadIdx.x;  // 0..NB*HH-1
    const int n = idx >> 8;
    const int j = idx & 255;
    const float* xr = xw + (size_t)n * ldxw;
    const float* gr = g + (size_t)n * G3;
    const float r  = 1.f / (1.f + expf(-(xr[j] + gr[j])));
    const float z  = 1.f / (1.f + expf(-(xr[HH + j] + gr[HH + j])));
    const float nn = tanhf(xr[2 * HH + j] + r * gr[2 * HH + j]);
    const float hn = (1.f - z) * nn + z * h[idx];
    h[idx] = hn;
    if (ys) ys[(size_t)n * ldys + j] = hn;
}

// ---------------------------------------------------------------------------
// Per-head projection: out[n,row,col] = sum_d A[row,d] * Wm[n,d,col] + bias[n,col]
// A is [M,256], Wm is (NH,256,128), out (NH,M,128). grid (8, ceil(M/16), NH).
// ---------------------------------------------------------------------------
__global__ void proj_kernel(const float* __restrict__ A, int M,
                            const float* __restrict__ Wm,
                            const float* __restrict__ bias,
                            float* __restrict__ out)
{
    const int head = blockIdx.z;
    const int col = blockIdx.x * 16 + threadIdx.x;
    const int row = blockIdx.y * 16 + threadIdx.y;
    const int rc = min(row, M - 1);
    const float* W = Wm + (size_t)head * HH * HD;
    __shared__ float As[16][17], Ws[16][17];
    float acc = 0.f;
    for (int k0 = 0; k0 < HH; k0 += 16) {
        As[threadIdx.y][threadIdx.x] = A[(size_t)rc * HH + k0 + threadIdx.x];
        Ws[threadIdx.y][threadIdx.x] = W[(size_t)(k0 + threadIdx.y) * HD + col];
        __syncthreads();
#pragma unroll
        for (int k = 0; k < 16; k++)
            acc += As[threadIdx.y][k] * Ws[k][threadIdx.x];
        __syncthreads();
    }
    if (row < M)
        out[((size_t)head * M + row) * HD + col] = acc + bias[head * HD + col];
}

// ---------------------------------------------------------------------------
// MHA1: B = attn(R, S, S). One block per (head, l in 30). 256 threads.
// Softmax over 2048 keys; output written as B[l, head*128+h].
// ---------------------------------------------------------------------------
__global__ void attn1_kernel(const float* __restrict__ qh,
                             const float* __restrict__ kh,
                             const float* __restrict__ vh,
                             float* __restrict__ B)
{
    const int head = blockIdx.x / CC;
    const int l = blockIdx.x % CC;
    const int tid = threadIdx.x;
    __shared__ float p[NB];
    __shared__ float q[HD];
    __shared__ float red[256];
    if (tid < HD) q[tid] = qh[((size_t)head * CC + l) * HD + tid];
    __syncthreads();
    const float scale = 0.08838834764831845f;  // 1/sqrt(128)
    float lmax = -1e30f;
    for (int k = tid; k < NB; k += 256) {
        const float* kr = kh + ((size_t)head * NB + k) * HD;
        float s = 0.f;
#pragma unroll 4
        for (int d = 0; d < HD; d++) s += q[d] * kr[d];
        s *= scale;
        p[k] = s;
        lmax = fmaxf(lmax, s);
    }
    red[tid] = lmax; __syncthreads();
    for (int s = 128; s > 0; s >>= 1) {
        if (tid < s) red[tid] = fmaxf(red[tid], red[tid + s]);
        __syncthreads();
    }
    const float m = red[0];
    __syncthreads();
    float lsum = 0.f;
    for (int k = tid; k < NB; k += 256) {
        const float e = expf(p[k] - m);
        p[k] = e;
        lsum += e;
    }
    red[tid] = lsum; __syncthreads();
    for (int s = 128; s > 0; s >>= 1) {
        if (tid < s) red[tid] += red[tid + s];
        __syncthreads();
    }
    const float inv = 1.f / red[0];
    __syncthreads();
    const int col = tid & 127;
    const int half = tid >> 7;
    float o = 0.f;
    for (int k = half * 1024; k < half * 1024 + 1024; k++)
        o += p[k] * vh[((size_t)head * NB + k) * HD + col];
    red[tid] = o; __syncthreads();
    if (tid < HD)
        B[l * (NHD * HD) + head * HD + tid] = (red[tid] + red[tid + 128]) * inv;
}

// ---------------------------------------------------------------------------
// MHA2: S' = attn(S, B, B). One block per (l in 2048, head). 128 threads.
// Only 30 keys -> softmax recomputed per thread (cheap).
// ---------------------------------------------------------------------------
__global__ void attn2_kernel(const float* __restrict__ qh,
                             const float* __restrict__ kh,
                             const float* __restrict__ vh,
                             float* __restrict__ Sp)
{
    const int l = blockIdx.x;
    const int head = blockIdx.y;
    const int tid = threadIdx.x;  // 0..127
    __shared__ float q[HD];
    __shared__ float sc[CC];
    q[tid] = qh[((size_t)head * NB + l) * HD + tid];
    __syncthreads();
    const float scale = 0.08838834764831845f;
    if (tid < CC) {
        const float* kr = kh + (head * CC + tid) * HD;
        float s = 0.f;
        for (int d = 0; d < HD; d++) s += q[d] * kr[d];
        sc[tid] = s * scale;
    }
    __syncthreads();
    float m = -1e30f;
#pragma unroll
    for (int k = 0; k < CC; k++) m = fmaxf(m, sc[k]);
    float sum = 0.f, o = 0.f;
#pragma unroll
    for (int k = 0; k < CC; k++) {
        const float e = expf(sc[k] - m);
        sum += e;
        o += e * vh[(head * CC + k) * HD + tid];
    }
    Sp[(size_t)l * HH + head * HD + tid] = o / sum;
}

// ---------------------------------------------------------------------------
// alpha = sigmoid(S . W_gate + b_gate); Smix = alpha*Sp + (1-alpha)*S
// ---------------------------------------------------------------------------
__global__ void gate_mix_kernel(const float* __restrict__ S,
                                const float* __restrict__ Sp,
                                const float* __restrict__ Wg,
                                const float* __restrict__ bg,
                                float* __restrict__ Smix)
{
    __shared__ float red[256];
    const int l = blockIdx.x, d = threadIdx.x;
    const float sv = S[(size_t)l * HH + d];
    red[d] = sv * Wg[d];
    __syncthreads();
    for (int s = 128; s > 0; s >>= 1) {
        if (d < s) red[d] += red[d + s];
        __syncthreads();
    }
    const float alpha = 1.f / (1.f + expf(-(red[0] + bg[0])));
    Smix[(size_t)l * HH + d] = alpha * Sp[(size_t)l * HH + d] + (1.f - alpha) * sv;
}

__global__ void relu_add_kernel(const float* __restrict__ mlp,
                                float* __restrict__ Smix)
{
    const int idx = blockIdx.x * blockDim.x + threadIdx.x;
    Smix[idx] += fmaxf(mlp[idx], 0.f);
}

__global__ void rowdot_kernel(const float* __restrict__ S,
                              const float* __restrict__ W2,
                              const float* __restrict__ b2,
                              float* __restrict__ y)
{
    __shared__ float red[256];
    const int l = blockIdx.x, tid = threadIdx.x;
    red[tid] = S[(size_t)l * HH + tid] * W2[tid];
    __syncthreads();
    for (int s = 128; s > 0; s >>= 1) {
        if (tid < s) red[tid] += red[tid + s];
        __syncthreads();
    }
    if (tid == 0) y[l] = red[0] + b2[0];
}

__global__ void normalize_kernel(const float* __restrict__ y,
                                 float* __restrict__ out)
{
    __shared__ float red[1024];
    const int tid = threadIdx.x;
    const float a = y[tid], b = y[tid + 1024];
    red[tid] = a + b; __syncthreads();
    for (int s = 512; s > 0; s >>= 1) {
        if (tid < s) red[tid] += red[tid + s];
        __syncthreads();
    }
    const float mean = red[0] * (1.f / 2048.f);
    __syncthreads();
    const float da = a - mean, db = b - mean;
    red[tid] = da * da + db * db; __syncthreads();
    for (int s = 512; s > 0; s >>= 1) {
        if (tid < s) red[tid] += red[tid + s];
        __syncthreads();
    }
    const float inv = 1.f / (sqrtf(red[0] / 2047.f) + 1e-8f);
    out[tid] = da * inv;
    out[tid + 1024] = db * inv;
}

// ---------------------------------------------------------------------------
// Host driver — all launches on the default stream, graph-capturable.
// ---------------------------------------------------------------------------
extern "C" void kernel_launch(void* const* d_in, const int* in_sizes, int n_in,
                              void* d_out, int out_size)
{
    const float* x      = (const float*)d_in[0];
    const float* W_ih0  = (const float*)d_in[1];
    const float* W_hh0  = (const float*)d_in[2];
    const float* b_ih0  = (const float*)d_in[3];
    const float* b_hh0  = (const float*)d_in[4];
    const float* W_ih1  = (const float*)d_in[5];
    const float* W_hh1  = (const float*)d_in[6];
    const float* b_ih1  = (const float*)d_in[7];
    const float* b_hh1  = (const float*)d_in[8];
    const float* Wq     = (const float*)d_in[9];
    const float* bq     = (const float*)d_in[10];
    const float* Wk     = (const float*)d_in[11];
    const float* bk     = (const float*)d_in[12];
    const float* Wv     = (const float*)d_in[13];
    const float* bv     = (const float*)d_in[14];
    const float* R      = (const float*)d_in[15];
    const float* W_gate = (const float*)d_in[16];
    const float* b_gate = (const float*)d_in[17];
    const float* W1     = (const float*)d_in[18];
    const float* b1     = (const float*)d_in[19];
    const float* W2     = (const float*)d_in[20];
    const float* b2     = (const float*)d_in[21];
    float* out = (float*)d_out;

    float *xw, *ys0, *gates, *h, *qh1, *kh1, *vh1, *Bb, *qh2, *kh2, *vh2;
    float *Sp, *Smix, *mlp, *yraw;
    cudaGetSymbolAddress((void**)&xw, g_xw);
    cudaGetSymbolAddress((void**)&ys0, g_ys0);
    cudaGetSymbolAddress((void**)&gates, g_gates);
    cudaGetSymbolAddress((void**)&h, g_h);
    cudaGetSymbolAddress((void**)&qh1, g_qh1);
    cudaGetSymbolAddress((void**)&kh1, g_kh1);
    cudaGetSymbolAddress((void**)&vh1, g_vh1);
    cudaGetSymbolAddress((void**)&Bb, g_B);
    cudaGetSymbolAddress((void**)&qh2, g_qh2);
    cudaGetSymbolAddress((void**)&kh2, g_kh2);
    cudaGetSymbolAddress((void**)&vh2, g_vh2);
    cudaGetSymbolAddress((void**)&Sp, g_Sp);
    cudaGetSymbolAddress((void**)&Smix, g_Smix);
    cudaGetSymbolAddress((void**)&mlp, g_mlp);
    cudaGetSymbolAddress((void**)&yraw, g_yraw);

    const dim3 blk2(16, 16);

    // ---- Layer 0: xW0 = x @ W_ih0^T + b_ih0  (262144 x 768, K=64) ----
    gemm_bias_kernel<<<dim3(G3 / 64, NTROWS / 64), blk2>>>(
        x, INDIM, W_ih0, b_ih0, xw, G3, NTROWS, G3, INDIM);
    cudaMemsetAsync(h, 0, (size_t)NB * HH * sizeof(float));
    for (int t = 0; t < TT; t++) {
        gemm_bias_kernel<<<dim3(G3 / 64, NB / 64), blk2>>>(
            h, HH, W_hh0, b_hh0, gates, G3, NB, G3, HH);
        gru_gate_kernel<<<NB, 256>>>(
            xw + (size_t)t * G3, (size_t)TT * G3, gates, h,
            ys0 + (size_t)t * HH, (size_t)TT * HH);
    }

    // ---- Layer 1: xW1 = ys0 @ W_ih1^T + b_ih1  (262144 x 768, K=256) ----
    gemm_bias_kernel<<<dim3(G3 / 64, NTROWS / 64), blk2>>>(
        ys0, HH, W_ih1, b_ih1, xw, G3, NTROWS, G3, HH);
    cudaMemsetAsync(h, 0, (size_t)NB * HH * sizeof(float));
    for (int t = 0; t < TT; t++) {
        gemm_bias_kernel<<<dim3(G3 / 64, NB / 64), blk2>>>(
            h, HH, W_hh1, b_hh1, gates, G3, NB, G3, HH);
        gru_gate_kernel<<<NB, 256>>>(
            xw + (size_t)t * G3, (size_t)TT * G3, gates, h, nullptr, 0);
    }
    // h now holds S = out[:, -1, :]

    // ---- Attention: B = MHA(R, S, S), S' = MHA(S, B, B) ----
    proj_kernel<<<dim3(8, 2, NHD), blk2>>>(R, CC, Wq, bq, qh1);
    proj_kernel<<<dim3(8, NB / 16, NHD), blk2>>>(h, NB, Wk, bk, kh1);
    proj_kernel<<<dim3(8, NB / 16, NHD), blk2>>>(h, NB, Wv, bv, vh1);
    attn1_kernel<<<NHD * CC, 256>>>(qh1, kh1, vh1, Bb);
    proj_kernel<<<dim3(8, NB / 16, NHD), blk2>>>(h, NB, Wq, bq, qh2);
    proj_kernel<<<dim3(8, 2, NHD), blk2>>>(Bb, CC, Wk, bk, kh2);
    proj_kernel<<<dim3(8, 2, NHD), blk2>>>(Bb, CC, Wv, bv, vh2);
    attn2_kernel<<<dim3(NB, NHD), 128>>>(qh2, kh2, vh2, Sp);

    // ---- Gate mix + MLP + output ----
    gate_mix_kernel<<<NB, 256>>>(h, Sp, W_gate, b_gate, Smix);
    gemm_bias_kernel<<<dim3(HH / 64, NB / 64), blk2>>>(
        Smix, HH, W1, b1, mlp, HH, NB, HH, HH);
    relu_add_kernel<<<(NB * HH) / 256, 256>>>(mlp, Smix);
    rowdot_kernel<<<NB, 256>>>(Smix, W2, b2, yraw);
    normalize_kernel<<<1, 1024>>>(yraw, out);
}

// round 5
// speedup vs baseline: 1.1660x; 1.1660x over previous
#include <cuda_runtime.h>
#include <cuda_bf16.h>
#include <math.h>

// ---------------------------------------------------------------------------
// Problem constants: N=2048, T=128, IN=64, H=256, 3H=768, NH=2, HD=128, C=30
// ---------------------------------------------------------------------------
#define NB    2048
#define TT    128
#define INDIM 64
#define HH    256
#define G3    768
#define NHD   2
#define HD    128
#define CC    30
#define NTROWS (NB * TT)   // 262144

typedef unsigned long long ull;

// ---------------------------------------------------------------------------
// Device scratch (allocation-free rule: __device__ globals)
// ---------------------------------------------------------------------------
__device__ float g_xw[(size_t)NTROWS * G3];   // xW for current layer
__device__ float g_ys0[(size_t)NTROWS * HH];  // layer-0 outputs
__device__ float g_S[NB * HH];                // final hidden state S
__device__ float g_wt_ih0[INDIM * G3];        // W_ih0^T  [64][768]
__device__ float g_wt_hh0[HH * G3];           // W_hh0^T  [256][768]
__device__ float g_wt_ih1[HH * G3];           // W_ih1^T  [256][768]
__device__ float g_wt_hh1[HH * G3];           // W_hh1^T  [256][768]
__device__ float g_wt_w1[HH * HH];            // W1^T     [256][256]
__device__ float g_qh1[NHD * CC * HD];
__device__ float g_kh1[NHD * NB * HD];
__device__ float g_vh1[NHD * NB * HD];
__device__ float g_B[CC * NHD * HD];
__device__ float g_qh2[NHD * NB * HD];
__device__ float g_kh2[NHD * CC * HD];
__device__ float g_vh2[NHD * CC * HD];
__device__ float g_Sp[NB * HH];
__device__ float g_Smix[NB * HH];
__device__ float g_mlp[NB * HH];
__device__ float g_yraw[NB];

// ---------------------------------------------------------------------------
// f32x2 packed-FMA helpers (Blackwell sm_100+: fma.rn.f32x2 on .b64 pairs)
// ---------------------------------------------------------------------------
__device__ __forceinline__ ull dup2(float a) {
    ull r;
    asm("mov.b64 %0, {%1, %1};" : "=l"(r) : "r"(__float_as_uint(a)));
    return r;
}
__device__ __forceinline__ void ffma2(ull& d, ull a, ull b) {
    asm("fma.rn.f32x2 %0, %1, %2, %0;" : "+l"(d) : "l"(a), "l"(b));
}
__device__ __forceinline__ float2 unpack2(ull v) {
    unsigned lo, hi;
    asm("mov.b64 {%0, %1}, %2;" : "=r"(lo), "=r"(hi) : "l"(v));
    return make_float2(__uint_as_float(lo), __uint_as_float(hi));
}
__device__ __forceinline__ float sigm_f(float x) {
    return 1.f / (1.f + __expf(-x));
}
__device__ __forceinline__ float tanh_f(float x) {
    // NaN-safe: e=inf -> 1, e=0 -> -1
    float e = __expf(2.f * x);
    return 1.f - 2.f / (e + 1.f);
}

// ---------------------------------------------------------------------------
// Transpose: in[R][C] -> out[C][R]. R,C multiples of 32.
// ---------------------------------------------------------------------------
__global__ void transpose_kernel(const float* __restrict__ in,
                                 float* __restrict__ out, int R, int C)
{
    __shared__ float t[32][33];
    const int c0 = blockIdx.x * 32, r0 = blockIdx.y * 32;
    for (int j = threadIdx.y; j < 32; j += 8)
        t[j][threadIdx.x] = in[(size_t)(r0 + j) * C + c0 + threadIdx.x];
    __syncthreads();
    for (int j = threadIdx.y; j < 32; j += 8)
        out[(size_t)(c0 + j) * R + r0 + threadIdx.x] = t[threadIdx.x][j];
}

// ---------------------------------------------------------------------------
// gemm2: C[M,Nn] = A[M,K] @ Wt[K,Nn] + bias[Nn], using f32x2 packed FMAs.
// BM=128, BN=128, BK=16, 256 threads, thread tile 8m x 8n (32 ull accs).
// A is duplicated in SMEM ({a,a} pairs) so ld.shared.b64 feeds FMA2 directly.
// Requires M%128==0, Nn%128==0, K%16==0.
// ---------------------------------------------------------------------------
#define S2 258   // AsD row stride in floats (2*128 data + 2 pad)

__global__ __launch_bounds__(256, 2) void gemm2_kernel(
    const float* __restrict__ A,
    const float* __restrict__ Wt,
    const float* __restrict__ bias,
    float* __restrict__ C,
    int M, int Nn, int K)
{
    __shared__ float AsD[16 * S2];     // duplicated A tile [k][2m]
    __shared__ float Ws[16 * 128];     // W tile [k][n]
    const int tid = threadIdx.x;
    const int row0 = blockIdx.y * 128;
    const int col0 = blockIdx.x * 128;
    const int ngrp = tid & 15, mgrp = tid >> 4;
    const int n0 = ngrp * 8, m0 = mgrp * 8;

    ull acc[8][4];
#pragma unroll
    for (int i = 0; i < 8; i++)
#pragma unroll
        for (int p = 0; p < 4; p++) acc[i][p] = 0ULL;

    for (int k0 = 0; k0 < K; k0 += 16) {
#pragma unroll
        for (int q = 0; q < 2; q++) {
            const int v = tid + q * 256;          // 0..511
            // A tile: 128 rows x 16 k = 512 float4
            const int rm = v >> 2, kc = (v & 3) << 2;
            float4 av = *(const float4*)(A + (size_t)(row0 + rm) * K + k0 + kc);
            *(ull*)&AsD[(kc + 0) * S2 + 2 * rm] = dup2(av.x);
            *(ull*)&AsD[(kc + 1) * S2 + 2 * rm] = dup2(av.y);
            *(ull*)&AsD[(kc + 2) * S2 + 2 * rm] = dup2(av.z);
            *(ull*)&AsD[(kc + 3) * S2 + 2 * rm] = dup2(av.w);
            // W tile: 16 k x 128 n = 512 float4
            const int rk = v >> 5, nc = (v & 31) << 2;
            *(float4*)&Ws[rk * 128 + nc] =
                *(const float4*)(Wt + (size_t)(k0 + rk) * Nn + col0 + nc);
        }
        __syncthreads();
#pragma unroll
        for (int k = 0; k < 16; k++) {
            ull w[4];
#pragma unroll
            for (int p = 0; p < 4; p++)
                w[p] = *(const ull*)&Ws[k * 128 + n0 + 2 * p];
#pragma unroll
            for (int i = 0; i < 8; i++) {
                ull ad = *(const ull*)&AsD[k * S2 + 2 * (m0 + i)];
#pragma unroll
                for (int p = 0; p < 4; p++) ffma2(acc[i][p], w[p], ad);
            }
        }
        __syncthreads();
    }

    const float4 b0 = *(const float4*)(bias + col0 + n0);
    const float4 b1 = *(const float4*)(bias + col0 + n0 + 4);
#pragma unroll
    for (int i = 0; i < 8; i++) {
        float* crow = C + (size_t)(row0 + m0 + i) * Nn + col0 + n0;
        float2 p0 = unpack2(acc[i][0]), p1 = unpack2(acc[i][1]);
        float2 p2 = unpack2(acc[i][2]), p3 = unpack2(acc[i][3]);
        *(float4*)(crow)     = make_float4(p0.x + b0.x, p0.y + b0.y,
                                           p1.x + b0.z, p1.y + b0.w);
        *(float4*)(crow + 4) = make_float4(p2.x + b1.x, p2.y + b1.y,
                                           p3.x + b1.z, p3.y + b1.w);
    }
}

// ---------------------------------------------------------------------------
// Persistent GRU layer: grid=128 CTAs x 256 threads; each CTA owns 16 batch
// rows for all 128 time steps. h lives in SMEM, stored DUPLICATED ({h,h}
// pairs) so the GEMM phase feeds fma.rn.f32x2 via a single ld.shared.b64.
// Per step:
//   1) cp.async prefetch of xW(t) slice (overlaps the recurrent GEMM)
//   2) G = h @ Whh^T + bhh   (f32x2, Whh^T streamed from L2)
//   3) fused gate math, h update, optional ys store
// ---------------------------------------------------------------------------
#define RBM  16
#define RPAD 776
// h duplicated: 16 x 512 floats; G_s and xw_s: 16 x 776 each
#define REC_SMEM ((RBM * 512 + 2 * RBM * RPAD) * 4)   // 132096 bytes

__global__ __launch_bounds__(256, 1) void gru_rec_kernel(
    const float* __restrict__ Wt,    // [256][768] = Whh^T
    const float* __restrict__ bhh,   // [768]
    const float* __restrict__ xw,    // [NTROWS][768], row = n*T + t
    float* __restrict__ ys,          // [NTROWS][256] or null
    float* __restrict__ hout)        // [NB][256] or null
{
    extern __shared__ float sm[];
    float* h2_s = sm;                          // 16 x 512 (duplicated pairs)
    float* G_s  = sm + RBM * 512;              // 16 x 776
    float* xw_s = G_s + RBM * RPAD;            // 16 x 776

    const int tid = threadIdx.x;
    const int n0 = blockIdx.x * RBM;

    // GEMM-phase mapping: 128 n-groups (6 cols) x 2 m-groups (8 rows)
    const int ng = tid & 127;
    const int mg = tid >> 7;
    const int gn0 = ng * 6;
    const int gm0 = mg * 8;
    // gate-phase mapping: 16 rows x 16 col-groups of 16
    const int qm = tid >> 4;
    const int qj = (tid & 15) << 4;

    // zero duplicated h
    for (int i = tid; i < RBM * 512; i += 256) h2_s[i] = 0.f;

    // bias pairs for this thread's 6 columns
    ull bh[3];
#pragma unroll
    for (int p = 0; p < 3; p++)
        bh[p] = *(const ull*)(bhh + gn0 + 2 * p);

    __syncthreads();

    for (int t = 0; t < TT; t++) {
        // ---- prefetch xW(t): 16 rows x 768 floats = 3072 float4
        //      (192 float4 per row) ----
#pragma unroll
        for (int c = 0; c < 12; c++) {
            const int v = tid + c * 256;          // 0..3071
            const int rm = v / 192;               // 0..15
            const int c4 = v - rm * 192;          // 0..191
            const float* src = xw + ((size_t)(n0 + rm) * TT + t) * G3 + c4 * 4;
            unsigned dst = (unsigned)__cvta_generic_to_shared(
                xw_s + rm * RPAD + c4 * 4);
            asm volatile("cp.async.ca.shared.global [%0], [%1], 16;"
                         :: "r"(dst), "l"(src));
        }
        asm volatile("cp.async.commit_group;" ::: "memory");

        // ---- G = h @ Whh^T + bhh (f32x2 pairs; h read as {h,h} LDS.64) ----
        ull acc[8][3];
#pragma unroll
        for (int i = 0; i < 8; i++) {
            acc[i][0] = bh[0]; acc[i][1] = bh[1]; acc[i][2] = bh[2];
        }
#pragma unroll 4
        for (int k = 0; k < HH; k++) {
            const ull* wr = (const ull*)(Wt + (size_t)k * G3 + gn0);
            const ull w0 = wr[0], w1 = wr[1], w2 = wr[2];
#pragma unroll
            for (int i = 0; i < 8; i++) {
                const ull hd = *(const ull*)&h2_s[(gm0 + i) * 512 + 2 * k];
                ffma2(acc[i][0], w0, hd);
                ffma2(acc[i][1], w1, hd);
                ffma2(acc[i][2], w2, hd);
            }
        }
#pragma unroll
        for (int i = 0; i < 8; i++) {
            float* grow = G_s + (gm0 + i) * RPAD + gn0;
#pragma unroll
            for (int p = 0; p < 3; p++) {
                float2 v = unpack2(acc[i][p]);
                *(float2*)(grow + 2 * p) = v;
            }
        }

        asm volatile("cp.async.wait_group 0;" ::: "memory");
        __syncthreads();

        // ---- fused gate update ----
        const float* xr = xw_s + qm * RPAD;
        const float* gr = G_s + qm * RPAD;
        float* hrow = h2_s + qm * 512;
        float hn[16];
#pragma unroll
        for (int j = 0; j < 16; j++) {
            const int jj = qj + j;
            const float r = sigm_f(xr[jj] + gr[jj]);
            const float z = sigm_f(xr[HH + jj] + gr[HH + jj]);
            const float nv = tanh_f(xr[2 * HH + jj] + r * gr[2 * HH + jj]);
            const float hold = hrow[2 * jj];
            hn[j] = (1.f - z) * nv + z * hold;
            *(float2*)&hrow[2 * jj] = make_float2(hn[j], hn[j]);
        }
        if (ys) {
            float4* dst = (float4*)(ys + ((size_t)(n0 + qm) * TT + t) * HH + qj);
#pragma unroll
            for (int q = 0; q < 4; q++)
                dst[q] = make_float4(hn[4 * q], hn[4 * q + 1],
                                     hn[4 * q + 2], hn[4 * q + 3]);
        }
        __syncthreads();
    }

    if (hout) {
#pragma unroll
        for (int q = 0; q < 4; q++) {
            float4 v = make_float4(h2_s[qm * 512 + 2 * (qj + 4 * q + 0)],
                                   h2_s[qm * 512 + 2 * (qj + 4 * q + 1)],
                                   h2_s[qm * 512 + 2 * (qj + 4 * q + 2)],
                                   h2_s[qm * 512 + 2 * (qj + 4 * q + 3)]);
            *(float4*)(hout + (size_t)(n0 + qm) * HH + qj + 4 * q) = v;
        }
    }
}

// ---------------------------------------------------------------------------
// Per-head projection: out[n,row,col] = A[row,:] . Wm[n,:,col] + bias[n,col]
// ---------------------------------------------------------------------------
__global__ void proj_kernel(const float* __restrict__ A, int M,
                            const float* __restrict__ Wm,
                            const float* __restrict__ bias,
                            float* __restrict__ out)
{
    const int head = blockIdx.z;
    const int col = blockIdx.x * 16 + threadIdx.x;
    const int row = blockIdx.y * 16 + threadIdx.y;
    const int rc = min(row, M - 1);
    const float* W = Wm + (size_t)head * HH * HD;
    __shared__ float As[16][17], Wsh[16][17];
    float acc = 0.f;
    for (int k0 = 0; k0 < HH; k0 += 16) {
        As[threadIdx.y][threadIdx.x] = A[(size_t)rc * HH + k0 + threadIdx.x];
        Wsh[threadIdx.y][threadIdx.x] = W[(size_t)(k0 + threadIdx.y) * HD + col];
        __syncthreads();
#pragma unroll
        for (int k = 0; k < 16; k++)
            acc += As[threadIdx.y][k] * Wsh[k][threadIdx.x];
        __syncthreads();
    }
    if (row < M)
        out[((size_t)head * M + row) * HD + col] = acc + bias[head * HD + col];
}

// ---------------------------------------------------------------------------
// MHA1: B = attn(R, S, S). One block per (head, l). 256 threads.
// ---------------------------------------------------------------------------
__global__ void attn1_kernel(const float* __restrict__ qh,
                             const float* __restrict__ kh,
                             const float* __restrict__ vh,
                             float* __restrict__ B)
{
    const int head = blockIdx.x / CC;
    const int l = blockIdx.x % CC;
    const int tid = threadIdx.x;
    __shared__ float p[NB];
    __shared__ float q[HD];
    __shared__ float red[256];
    if (tid < HD) q[tid] = qh[((size_t)head * CC + l) * HD + tid];
    __syncthreads();
    const float scale = 0.08838834764831845f;
    float lmax = -1e30f;
    for (int k = tid; k < NB; k += 256) {
        const float* kr = kh + ((size_t)head * NB + k) * HD;
        float s = 0.f;
#pragma unroll 4
        for (int d = 0; d < HD; d++) s += q[d] * kr[d];
        s *= scale;
        p[k] = s;
        lmax = fmaxf(lmax, s);
    }
    red[tid] = lmax; __syncthreads();
    for (int s = 128; s > 0; s >>= 1) {
        if (tid < s) red[tid] = fmaxf(red[tid], red[tid + s]);
        __syncthreads();
    }
    const float m = red[0];
    __syncthreads();
    float lsum = 0.f;
    for (int k = tid; k < NB; k += 256) {
        const float e = expf(p[k] - m);
        p[k] = e;
        lsum += e;
    }
    red[tid] = lsum; __syncthreads();
    for (int s = 128; s > 0; s >>= 1) {
        if (tid < s) red[tid] += red[tid + s];
        __syncthreads();
    }
    const float inv = 1.f / red[0];
    __syncthreads();
    const int col = tid & 127;
    const int half = tid >> 7;
    float o = 0.f;
    for (int k = half * 1024; k < half * 1024 + 1024; k++)
        o += p[k] * vh[((size_t)head * NB + k) * HD + col];
    red[tid] = o; __syncthreads();
    if (tid < HD)
        B[l * (NHD * HD) + head * HD + tid] = (red[tid] + red[tid + 128]) * inv;
}

// ---------------------------------------------------------------------------
// MHA2: S' = attn(S, B, B). One block per (l, head). 128 threads, 30 keys.
// ---------------------------------------------------------------------------
__global__ void attn2_kernel(const float* __restrict__ qh,
                             const float* __restrict__ kh,
                             const float* __restrict__ vh,
                             float* __restrict__ Sp)
{
    const int l = blockIdx.x;
    const int head = blockIdx.y;
    const int tid = threadIdx.x;
    __shared__ float q[HD];
    __shared__ float sc[CC];
    q[tid] = qh[((size_t)head * NB + l) * HD + tid];
    __syncthreads();
    const float scale = 0.08838834764831845f;
    if (tid < CC) {
        const float* kr = kh + (head * CC + tid) * HD;
        float s = 0.f;
        for (int d = 0; d < HD; d++) s += q[d] * kr[d];
        sc[tid] = s * scale;
    }
    __syncthreads();
    float m = -1e30f;
#pragma unroll
    for (int k = 0; k < CC; k++) m = fmaxf(m, sc[k]);
    float sum = 0.f, o = 0.f;
#pragma unroll
    for (int k = 0; k < CC; k++) {
        const float e = expf(sc[k] - m);
        sum += e;
        o += e * vh[(head * CC + k) * HD + tid];
    }
    Sp[(size_t)l * HH + head * HD + tid] = o / sum;
}

__global__ void gate_mix_kernel(const float* __restrict__ S,
                                const float* __restrict__ Sp,
                                const float* __restrict__ Wg,
                                const float* __restrict__ bg,
                                float* __restrict__ Smix)
{
    __shared__ float red[256];
    const int l = blockIdx.x, d = threadIdx.x;
    const float sv = S[(size_t)l * HH + d];
    red[d] = sv * Wg[d];
    __syncthreads();
    for (int s = 128; s > 0; s >>= 1) {
        if (d < s) red[d] += red[d + s];
        __syncthreads();
    }
    const float alpha = 1.f / (1.f + expf(-(red[0] + bg[0])));
    Smix[(size_t)l * HH + d] = alpha * Sp[(size_t)l * HH + d] + (1.f - alpha) * sv;
}

__global__ void relu_add_kernel(const float* __restrict__ mlp,
                                float* __restrict__ Smix)
{
    const int idx = blockIdx.x * blockDim.x + threadIdx.x;
    Smix[idx] += fmaxf(mlp[idx], 0.f);
}

__global__ void rowdot_kernel(const float* __restrict__ S,
                              const float* __restrict__ W2,
                              const float* __restrict__ b2,
                              float* __restrict__ y)
{
    __shared__ float red[256];
    const int l = blockIdx.x, tid = threadIdx.x;
    red[tid] = S[(size_t)l * HH + tid] * W2[tid];
    __syncthreads();
    for (int s = 128; s > 0; s >>= 1) {
        if (tid < s) red[tid] += red[tid + s];
        __syncthreads();
    }
    if (tid == 0) y[l] = red[0] + b2[0];
}

__global__ void normalize_kernel(const float* __restrict__ y,
                                 float* __restrict__ out)
{
    __shared__ float red[1024];
    const int tid = threadIdx.x;
    const float a = y[tid], b = y[tid + 1024];
    red[tid] = a + b; __syncthreads();
    for (int s = 512; s > 0; s >>= 1) {
        if (tid < s) red[tid] += red[tid + s];
        __syncthreads();
    }
    const float mean = red[0] * (1.f / 2048.f);
    __syncthreads();
    const float da = a - mean, db = b - mean;
    red[tid] = da * da + db * db; __syncthreads();
    for (int s = 512; s > 0; s >>= 1) {
        if (tid < s) red[tid] += red[tid + s];
        __syncthreads();
    }
    const float inv = 1.f / (sqrtf(red[0] / 2047.f) + 1e-8f);
    out[tid] = da * inv;
    out[tid + 1024] = db * inv;
}

// ---------------------------------------------------------------------------
// Host driver — default stream, graph-capturable.
// ---------------------------------------------------------------------------
extern "C" void kernel_launch(void* const* d_in, const int* in_sizes, int n_in,
                              void* d_out, int out_size)
{
    const float* x      = (const float*)d_in[0];
    const float* W_ih0  = (const float*)d_in[1];
    const float* W_hh0  = (const float*)d_in[2];
    const float* b_ih0  = (const float*)d_in[3];
    const float* b_hh0  = (const float*)d_in[4];
    const float* W_ih1  = (const float*)d_in[5];
    const float* W_hh1  = (const float*)d_in[6];
    const float* b_ih1  = (const float*)d_in[7];
    const float* b_hh1  = (const float*)d_in[8];
    const float* Wq     = (const float*)d_in[9];
    const float* bq     = (const float*)d_in[10];
    const float* Wk     = (const float*)d_in[11];
    const float* bk     = (const float*)d_in[12];
    const float* Wv     = (const float*)d_in[13];
    const float* bv     = (const float*)d_in[14];
    const float* R      = (const float*)d_in[15];
    const float* W_gate = (const float*)d_in[16];
    const float* b_gate = (const float*)d_in[17];
    const float* W1     = (const float*)d_in[18];
    const float* b1     = (const float*)d_in[19];
    const float* W2     = (const float*)d_in[20];
    const float* b2     = (const float*)d_in[21];
    float* out = (float*)d_out;

    float *xw, *ys0, *S, *wt_ih0, *wt_hh0, *wt_ih1, *wt_hh1, *wt_w1;
    float *qh1, *kh1, *vh1, *Bb, *qh2, *kh2, *vh2, *Sp, *Smix, *mlp, *yraw;
    cudaGetSymbolAddress((void**)&xw, g_xw);
    cudaGetSymbolAddress((void**)&ys0, g_ys0);
    cudaGetSymbolAddress((void**)&S, g_S);
    cudaGetSymbolAddress((void**)&wt_ih0, g_wt_ih0);
    cudaGetSymbolAddress((void**)&wt_hh0, g_wt_hh0);
    cudaGetSymbolAddress((void**)&wt_ih1, g_wt_ih1);
    cudaGetSymbolAddress((void**)&wt_hh1, g_wt_hh1);
    cudaGetSymbolAddress((void**)&wt_w1, g_wt_w1);
    cudaGetSymbolAddress((void**)&qh1, g_qh1);
    cudaGetSymbolAddress((void**)&kh1, g_kh1);
    cudaGetSymbolAddress((void**)&vh1, g_vh1);
    cudaGetSymbolAddress((void**)&Bb, g_B);
    cudaGetSymbolAddress((void**)&qh2, g_qh2);
    cudaGetSymbolAddress((void**)&kh2, g_kh2);
    cudaGetSymbolAddress((void**)&vh2, g_vh2);
    cudaGetSymbolAddress((void**)&Sp, g_Sp);
    cudaGetSymbolAddress((void**)&Smix, g_Smix);
    cudaGetSymbolAddress((void**)&mlp, g_mlp);
    cudaGetSymbolAddress((void**)&yraw, g_yraw);

    cudaFuncSetAttribute(gru_rec_kernel,
                         cudaFuncAttributeMaxDynamicSharedMemorySize, REC_SMEM);

    const dim3 blk2(16, 16);
    const dim3 tb(32, 8);

    // ---- weight transposes (tiny) ----
    transpose_kernel<<<dim3(INDIM / 32, G3 / 32), tb>>>(W_ih0, wt_ih0, G3, INDIM);
    transpose_kernel<<<dim3(HH / 32, G3 / 32), tb>>>(W_hh0, wt_hh0, G3, HH);
    transpose_kernel<<<dim3(HH / 32, G3 / 32), tb>>>(W_ih1, wt_ih1, G3, HH);
    transpose_kernel<<<dim3(HH / 32, G3 / 32), tb>>>(W_hh1, wt_hh1, G3, HH);
    transpose_kernel<<<dim3(HH / 32, HH / 32), tb>>>(W1, wt_w1, HH, HH);

    // ---- Layer 0 ----
    gemm2_kernel<<<dim3(G3 / 128, NTROWS / 128), 256>>>(
        x, wt_ih0, b_ih0, xw, NTROWS, G3, INDIM);
    gru_rec_kernel<<<NB / RBM, 256, REC_SMEM>>>(
        wt_hh0, b_hh0, xw, ys0, nullptr);

    // ---- Layer 1 ----
    gemm2_kernel<<<dim3(G3 / 128, NTROWS / 128), 256>>>(
        ys0, wt_ih1, b_ih1, xw, NTROWS, G3, HH);
    gru_rec_kernel<<<NB / RBM, 256, REC_SMEM>>>(
        wt_hh1, b_hh1, xw, nullptr, S);

    // ---- Attention: B = MHA(R, S, S), S' = MHA(S, B, B) ----
    proj_kernel<<<dim3(8, 2, NHD), blk2>>>(R, CC, Wq, bq, qh1);
    proj_kernel<<<dim3(8, NB / 16, NHD), blk2>>>(S, NB, Wk, bk, kh1);
    proj_kernel<<<dim3(8, NB / 16, NHD), blk2>>>(S, NB, Wv, bv, vh1);
    attn1_kernel<<<NHD * CC, 256>>>(qh1, kh1, vh1, Bb);
    proj_kernel<<<dim3(8, NB / 16, NHD), blk2>>>(S, NB, Wq, bq, qh2);
    proj_kernel<<<dim3(8, 2, NHD), blk2>>>(Bb, CC, Wk, bk, kh2);
    proj_kernel<<<dim3(8, 2, NHD), blk2>>>(Bb, CC, Wv, bv, vh2);
    attn2_kernel<<<dim3(NB, NHD), 128>>>(qh2, kh2, vh2, Sp);

    // ---- Gate mix + MLP + output ----
    gate_mix_kernel<<<NB, 256>>>(S, Sp, W_gate, b_gate, Smix);
    gemm2_kernel<<<dim3(HH / 128, NB / 128), 256>>>(
        Smix, wt_w1, b1, mlp, NB, HH, HH);
    relu_add_kernel<<<(NB * HH) / 256, 256>>>(mlp, Smix);
    rowdot_kernel<<<NB, 256>>>(Smix, W2, b2, yraw);
    normalize_kernel<<<1, 1024>>>(yraw, out);
}

// round 8
// speedup vs baseline: 1.3881x; 1.1906x over previous
#include <cuda_runtime.h>
#include <cuda_bf16.h>
#include <math.h>

// ---------------------------------------------------------------------------
// Problem constants: N=2048, T=128, IN=64, H=256, 3H=768, NH=2, HD=128, C=30
// ---------------------------------------------------------------------------
#define NB    2048
#define TT    128
#define INDIM 64
#define HH    256
#define G3    768
#define NHD   2
#define HD    128
#define CC    30
#define NTROWS (NB * TT)   // 262144

typedef unsigned long long ull;

// ---------------------------------------------------------------------------
// Device scratch (allocation-free rule: __device__ globals)
// ---------------------------------------------------------------------------
__device__ float g_xw[(size_t)NTROWS * G3];   // xW for current layer
__device__ float g_ys0[(size_t)NTROWS * HH];  // layer-0 outputs
__device__ float g_S[NB * HH];                // final hidden state S
__device__ float g_wt_ih0[INDIM * G3];        // W_ih0^T  [64][768]
__device__ float g_wt_hh0[HH * G3];           // W_hh0^T  [256][768]
__device__ float g_wt_ih1[HH * G3];           // W_ih1^T  [256][768]
__device__ float g_wt_hh1[HH * G3];           // W_hh1^T  [256][768]
__device__ float g_wt_w1[HH * HH];            // W1^T     [256][256]
__device__ float g_qh1[NHD * CC * HD];
__device__ float g_kh1[NHD * NB * HD];
__device__ float g_vh1[NHD * NB * HD];
__device__ float g_B[CC * NHD * HD];
__device__ float g_qh2[NHD * NB * HD];
__device__ float g_kh2[NHD * CC * HD];
__device__ float g_vh2[NHD * CC * HD];
__device__ float g_Sp[NB * HH];
__device__ float g_Smix[NB * HH];
__device__ float g_mlp[NB * HH];
__device__ float g_yraw[NB];

// ---------------------------------------------------------------------------
// f32x2 packed-FMA helpers (Blackwell sm_100+: fma.rn.f32x2 on .b64 pairs)
// ---------------------------------------------------------------------------
__device__ __forceinline__ ull dup2(float a) {
    ull r;
    asm("mov.b64 %0, {%1, %1};" : "=l"(r) : "r"(__float_as_uint(a)));
    return r;
}
__device__ __forceinline__ void ffma2(ull& d, ull a, ull b) {
    asm("fma.rn.f32x2 %0, %1, %2, %0;" : "+l"(d) : "l"(a), "l"(b));
}
__device__ __forceinline__ float2 unpack2(ull v) {
    unsigned lo, hi;
    asm("mov.b64 {%0, %1}, %2;" : "=r"(lo), "=r"(hi) : "l"(v));
    return make_float2(__uint_as_float(lo), __uint_as_float(hi));
}
__device__ __forceinline__ float sigm_f(float x) {
    return 1.f / (1.f + __expf(-x));
}
__device__ __forceinline__ float tanh_f(float x) {
    float e = __expf(2.f * x);
    return 1.f - 2.f / (e + 1.f);
}

// ---------------------------------------------------------------------------
// Transpose: in[R][C] -> out[C][R]. R,C multiples of 32.
// ---------------------------------------------------------------------------
__global__ void transpose_kernel(const float* __restrict__ in,
                                 float* __restrict__ out, int R, int C)
{
    __shared__ float t[32][33];
    const int c0 = blockIdx.x * 32, r0 = blockIdx.y * 32;
    for (int j = threadIdx.y; j < 32; j += 8)
        t[j][threadIdx.x] = in[(size_t)(r0 + j) * C + c0 + threadIdx.x];
    __syncthreads();
    for (int j = threadIdx.y; j < 32; j += 8)
        out[(size_t)(c0 + j) * R + r0 + threadIdx.x] = t[threadIdx.x][j];
}

// ---------------------------------------------------------------------------
// gemm2: C[M,Nn] = A[M,K] @ Wt[K,Nn] + bias[Nn], f32x2 packed FMAs.
// BM=128, BN=128, BK=16, 256 threads, thread tile 8m x (4 pairs strided 32).
// Thread (ngrp,mgrp): columns {2*ngrp + 32p} p=0..3 -> conflict-free LDS.64
// on Ws (lane-contiguous), coalesced float2 stores.
// ---------------------------------------------------------------------------
#define S2 258   // AsD row stride in floats (2*128 data + 2 pad)

__global__ __launch_bounds__(256, 2) void gemm2_kernel(
    const float* __restrict__ A,
    const float* __restrict__ Wt,
    const float* __restrict__ bias,
    float* __restrict__ C,
    int M, int Nn, int K)
{
    __shared__ float AsD[16 * S2];     // duplicated A tile [k][2m]
    __shared__ float Ws[16 * 128];     // W tile [k][n]
    const int tid = threadIdx.x;
    const int row0 = blockIdx.y * 128;
    const int col0 = blockIdx.x * 128;
    const int ngrp = tid & 15, mgrp = tid >> 4;
    const int m0 = mgrp * 8;
    const int nc0 = 2 * ngrp;          // base column pair offset

    ull acc[8][4];
#pragma unroll
    for (int i = 0; i < 8; i++)
#pragma unroll
        for (int p = 0; p < 4; p++) acc[i][p] = 0ULL;

    for (int k0 = 0; k0 < K; k0 += 16) {
#pragma unroll
        for (int q = 0; q < 2; q++) {
            const int v = tid + q * 256;          // 0..511
            // A tile: 128 rows x 16 k = 512 float4
            const int rm = v >> 2, kc = (v & 3) << 2;
            float4 av = *(const float4*)(A + (size_t)(row0 + rm) * K + k0 + kc);
            *(ull*)&AsD[(kc + 0) * S2 + 2 * rm] = dup2(av.x);
            *(ull*)&AsD[(kc + 1) * S2 + 2 * rm] = dup2(av.y);
            *(ull*)&AsD[(kc + 2) * S2 + 2 * rm] = dup2(av.z);
            *(ull*)&AsD[(kc + 3) * S2 + 2 * rm] = dup2(av.w);
            // W tile: 16 k x 128 n = 512 float4
            const int rk = v >> 5, nc = (v & 31) << 2;
            *(float4*)&Ws[rk * 128 + nc] =
                *(const float4*)(Wt + (size_t)(k0 + rk) * Nn + col0 + nc);
        }
        __syncthreads();
#pragma unroll
        for (int k = 0; k < 16; k++) {
            ull w[4];
#pragma unroll
            for (int p = 0; p < 4; p++)
                w[p] = *(const ull*)&Ws[k * 128 + nc0 + 32 * p];
#pragma unroll
            for (int i = 0; i < 8; i++) {
                ull ad = *(const ull*)&AsD[k * S2 + 2 * (m0 + i)];
#pragma unroll
                for (int p = 0; p < 4; p++) ffma2(acc[i][p], w[p], ad);
            }
        }
        __syncthreads();
    }

    float2 bp[4];
#pragma unroll
    for (int p = 0; p < 4; p++)
        bp[p] = *(const float2*)(bias + col0 + nc0 + 32 * p);
#pragma unroll
    for (int i = 0; i < 8; i++) {
        float* crow = C + (size_t)(row0 + m0 + i) * Nn + col0;
#pragma unroll
        for (int p = 0; p < 4; p++) {
            float2 v = unpack2(acc[i][p]);
            *(float2*)(crow + nc0 + 32 * p) =
                make_float2(v.x + bp[p].x, v.y + bp[p].y);
        }
    }
}

// ---------------------------------------------------------------------------
// Persistent GRU layer: 128 CTAs x 512 threads; each CTA owns 16 batch rows
// for all 128 steps. h lives in SMEM duplicated ({h,h} pairs -> LDS.64 feeds
// fma.rn.f32x2). Thread ng owns column pairs {2ng, 2ng+1} + 256p (p=0..2) so
// every Wt LDG.64 is lane-contiguous (2 wavefronts, not 7).
// ---------------------------------------------------------------------------
#define RBM  16
#define RPAD 776
#define RTHREADS 512
#define REC_SMEM ((RBM * 512 + 2 * RBM * RPAD) * 4)   // 132096 bytes

__global__ __launch_bounds__(RTHREADS, 1) void gru_rec_kernel(
    const float* __restrict__ Wt,    // [256][768] = Whh^T
    const float* __restrict__ bhh,   // [768]
    const float* __restrict__ xw,    // [NTROWS][768], row = n*T + t
    float* __restrict__ ys,          // [NTROWS][256] or null
    float* __restrict__ hout)        // [NB][256] or null
{
    extern __shared__ float sm[];
    float* h2_s = sm;                          // 16 x 512 (duplicated pairs)
    float* G_s  = sm + RBM * 512;              // 16 x 776
    float* xw_s = G_s + RBM * RPAD;            // 16 x 776

    const int tid = threadIdx.x;
    const int n0 = blockIdx.x * RBM;

    // GEMM-phase mapping: 128 n-threads x 4 m-groups of 4 rows
    const int ng = tid & 127;
    const int mg = tid >> 7;                   // 0..3
    const int gm0 = mg * 4;
    const int nc0 = 2 * ng;                    // column pair base
    // gate-phase mapping: 16 rows x 32 col-groups of 8
    const int qm = tid >> 5;                   // 0..15
    const int qj = (tid & 31) << 3;            // 0..248

    for (int i = tid; i < RBM * 512; i += RTHREADS) h2_s[i] = 0.f;

    ull bh[3];
#pragma unroll
    for (int p = 0; p < 3; p++)
        bh[p] = *(const ull*)(bhh + nc0 + 256 * p);

    __syncthreads();

    for (int t = 0; t < TT; t++) {
        // ---- prefetch xW(t): 16 rows x 192 float4 = 3072 float4 ----
#pragma unroll
        for (int c = 0; c < 6; c++) {
            const int v = tid + c * RTHREADS;     // 0..3071
            const int rm = v / 192;               // 0..15
            const int c4 = v - rm * 192;          // 0..191
            const float* src = xw + ((size_t)(n0 + rm) * TT + t) * G3 + c4 * 4;
            unsigned dst = (unsigned)__cvta_generic_to_shared(
                xw_s + rm * RPAD + c4 * 4);
            asm volatile("cp.async.ca.shared.global [%0], [%1], 16;"
                         :: "r"(dst), "l"(src));
        }
        asm volatile("cp.async.commit_group;" ::: "memory");

        // ---- G = h @ Whh^T + bhh (f32x2; coalesced Wt LDG.64) ----
        ull acc[4][3];
#pragma unroll
        for (int i = 0; i < 4; i++) {
            acc[i][0] = bh[0]; acc[i][1] = bh[1]; acc[i][2] = bh[2];
        }
#pragma unroll 4
        for (int k = 0; k < HH; k++) {
            const float* wrow = Wt + (size_t)k * G3 + nc0;
            const ull w0 = *(const ull*)(wrow);
            const ull w1 = *(const ull*)(wrow + 256);
            const ull w2 = *(const ull*)(wrow + 512);
#pragma unroll
            for (int i = 0; i < 4; i++) {
                const ull hd = *(const ull*)&h2_s[(gm0 + i) * 512 + 2 * k];
                ffma2(acc[i][0], w0, hd);
                ffma2(acc[i][1], w1, hd);
                ffma2(acc[i][2], w2, hd);
            }
        }
#pragma unroll
        for (int i = 0; i < 4; i++) {
            float* grow = G_s + (gm0 + i) * RPAD + nc0;
#pragma unroll
            for (int p = 0; p < 3; p++) {
                float2 v = unpack2(acc[i][p]);
                *(float2*)(grow + 256 * p) = v;
            }
        }

        asm volatile("cp.async.wait_group 0;" ::: "memory");
        __syncthreads();

        // ---- fused gate update (8 cols per thread) ----
        const float* xr = xw_s + qm * RPAD;
        const float* gr = G_s + qm * RPAD;
        float* hrow = h2_s + qm * 512;
        float hn[8];
#pragma unroll
        for (int j = 0; j < 8; j++) {
            const int jj = qj + j;
            const float r = sigm_f(xr[jj] + gr[jj]);
            const float z = sigm_f(xr[HH + jj] + gr[HH + jj]);
            const float nv = tanh_f(xr[2 * HH + jj] + r * gr[2 * HH + jj]);
            const float hold = hrow[2 * jj];
            hn[j] = (1.f - z) * nv + z * hold;
            *(float2*)&hrow[2 * jj] = make_float2(hn[j], hn[j]);
        }
        if (ys) {
            float4* dst = (float4*)(ys + ((size_t)(n0 + qm) * TT + t) * HH + qj);
            dst[0] = make_float4(hn[0], hn[1], hn[2], hn[3]);
            dst[1] = make_float4(hn[4], hn[5], hn[6], hn[7]);
        }
        __syncthreads();
    }

    if (hout) {
        float* dst = hout + (size_t)(n0 + qm) * HH + qj;
        const float* hrow = h2_s + qm * 512;
        *(float4*)(dst)     = make_float4(hrow[2 * (qj + 0)], hrow[2 * (qj + 1)],
                                          hrow[2 * (qj + 2)], hrow[2 * (qj + 3)]);
        *(float4*)(dst + 4) = make_float4(hrow[2 * (qj + 4)], hrow[2 * (qj + 5)],
                                          hrow[2 * (qj + 6)], hrow[2 * (qj + 7)]);
    }
}

// ---------------------------------------------------------------------------
// Per-head projection: out[n,row,col] = A[row,:] . Wm[n,:,col] + bias[n,col]
// ---------------------------------------------------------------------------
__global__ void proj_kernel(const float* __restrict__ A, int M,
                            const float* __restrict__ Wm,
                            const float* __restrict__ bias,
                            float* __restrict__ out)
{
    const int head = blockIdx.z;
    const int col = blockIdx.x * 16 + threadIdx.x;
    const int row = blockIdx.y * 16 + threadIdx.y;
    const int rc = min(row, M - 1);
    const float* W = Wm + (size_t)head * HH * HD;
    __shared__ float As[16][17], Wsh[16][17];
    float acc = 0.f;
    for (int k0 = 0; k0 < HH; k0 += 16) {
        As[threadIdx.y][threadIdx.x] = A[(size_t)rc * HH + k0 + threadIdx.x];
        Wsh[threadIdx.y][threadIdx.x] = W[(size_t)(k0 + threadIdx.y) * HD + col];
        __syncthreads();
#pragma unroll
        for (int k = 0; k < 16; k++)
            acc += As[threadIdx.y][k] * Wsh[k][threadIdx.x];
        __syncthreads();
    }
    if (row < M)
        out[((size_t)head * M + row) * HD + col] = acc + bias[head * HD + col];
}

// ---------------------------------------------------------------------------
// MHA1: B = attn(R, S, S). One block per (head, l). 256 threads.
// ---------------------------------------------------------------------------
__global__ void attn1_kernel(const float* __restrict__ qh,
                             const float* __restrict__ kh,
                             const float* __restrict__ vh,
                             float* __restrict__ B)
{
    const int head = blockIdx.x / CC;
    const int l = blockIdx.x % CC;
    const int tid = threadIdx.x;
    __shared__ float p[NB];
    __shared__ float q[HD];
    __shared__ float red[256];
    if (tid < HD) q[tid] = qh[((size_t)head * CC + l) * HD + tid];
    __syncthreads();
    const float scale = 0.08838834764831845f;
    float lmax = -1e30f;
    for (int k = tid; k < NB; k += 256) {
        const float* kr = kh + ((size_t)head * NB + k) * HD;
        float s = 0.f;
#pragma unroll 4
        for (int d = 0; d < HD; d++) s += q[d] * kr[d];
        s *= scale;
        p[k] = s;
        lmax = fmaxf(lmax, s);
    }
    red[tid] = lmax; __syncthreads();
    for (int s = 128; s > 0; s >>= 1) {
        if (tid < s) red[tid] = fmaxf(red[tid], red[tid + s]);
        __syncthreads();
    }
    const float m = red[0];
    __syncthreads();
    float lsum = 0.f;
    for (int k = tid; k < NB; k += 256) {
        const float e = expf(p[k] - m);
        p[k] = e;
        lsum += e;
    }
    red[tid] = lsum; __syncthreads();
    for (int s = 128; s > 0; s >>= 1) {
        if (tid < s) red[tid] += red[tid + s];
        __syncthreads();
    }
    const float inv = 1.f / red[0];
    __syncthreads();
    const int col = tid & 127;
    const int half = tid >> 7;
    float o = 0.f;
    for (int k = half * 1024; k < half * 1024 + 1024; k++)
        o += p[k] * vh[((size_t)head * NB + k) * HD + col];
    red[tid] = o; __syncthreads();
    if (tid < HD)
        B[l * (NHD * HD) + head * HD + tid] = (red[tid] + red[tid + 128]) * inv;
}

// ---------------------------------------------------------------------------
// MHA2: S' = attn(S, B, B). One block per (l, head). 128 threads, 30 keys.
// ---------------------------------------------------------------------------
__global__ void attn2_kernel(const float* __restrict__ qh,
                             const float* __restrict__ kh,
                             const float* __restrict__ vh,
                             float* __restrict__ Sp)
{
    const int l = blockIdx.x;
    const int head = blockIdx.y;
    const int tid = threadIdx.x;
    __shared__ float q[HD];
    __shared__ float sc[CC];
    q[tid] = qh[((size_t)head * NB + l) * HD + tid];
    __syncthreads();
    const float scale = 0.08838834764831845f;
    if (tid < CC) {
        const float* kr = kh + (head * CC + tid) * HD;
        float s = 0.f;
        for (int d = 0; d < HD; d++) s += q[d] * kr[d];
        sc[tid] = s * scale;
    }
    __syncthreads();
    float m = -1e30f;
#pragma unroll
    for (int k = 0; k < CC; k++) m = fmaxf(m, sc[k]);
    float sum = 0.f, o = 0.f;
#pragma unroll
    for (int k = 0; k < CC; k++) {
        const float e = expf(sc[k] - m);
        sum += e;
        o += e * vh[(head * CC + k) * HD + tid];
    }
    Sp[(size_t)l * HH + head * HD + tid] = o / sum;
}

__global__ void gate_mix_kernel(const float* __restrict__ S,
                                const float* __restrict__ Sp,
                                const float* __restrict__ Wg,
                                const float* __restrict__ bg,
                                float* __restrict__ Smix)
{
    __shared__ float red[256];
    const int l = blockIdx.x, d = threadIdx.x;
    const float sv = S[(size_t)l * HH + d];
    red[d] = sv * Wg[d];
    __syncthreads();
    for (int s = 128; s > 0; s >>= 1) {
        if (d < s) red[d] += red[d + s];
        __syncthreads();
    }
    const float alpha = 1.f / (1.f + expf(-(red[0] + bg[0])));
    Smix[(size_t)l * HH + d] = alpha * Sp[(size_t)l * HH + d] + (1.f - alpha) * sv;
}

__global__ void relu_add_kernel(const float* __restrict__ mlp,
                                float* __restrict__ Smix)
{
    const int idx = blockIdx.x * blockDim.x + threadIdx.x;
    Smix[idx] += fmaxf(mlp[idx], 0.f);
}

__global__ void rowdot_kernel(const float* __restrict__ S,
                              const float* __restrict__ W2,
                              const float* __restrict__ b2,
                              float* __restrict__ y)
{
    __shared__ float red[256];
    const int l = blockIdx.x, tid = threadIdx.x;
    red[tid] = S[(size_t)l * HH + tid] * W2[tid];
    __syncthreads();
    for (int s = 128; s > 0; s >>= 1) {
        if (tid < s) red[tid] += red[tid + s];
        __syncthreads();
    }
    if (tid == 0) y[l] = red[0] + b2[0];
}

__global__ void normalize_kernel(const float* __restrict__ y,
                                 float* __restrict__ out)
{
    __shared__ float red[1024];
    const int tid = threadIdx.x;
    const float a = y[tid], b = y[tid + 1024];
    red[tid] = a + b; __syncthreads();
    for (int s = 512; s > 0; s >>= 1) {
        if (tid < s) red[tid] += red[tid + s];
        __syncthreads();
    }
    const float mean = red[0] * (1.f / 2048.f);
    __syncthreads();
    const float da = a - mean, db = b - mean;
    red[tid] = da * da + db * db; __syncthreads();
    for (int s = 512; s > 0; s >>= 1) {
        if (tid < s) red[tid] += red[tid + s];
        __syncthreads();
    }
    const float inv = 1.f / (sqrtf(red[0] / 2047.f) + 1e-8f);
    out[tid] = da * inv;
    out[tid + 1024] = db * inv;
}

// ---------------------------------------------------------------------------
// Host driver — default stream, graph-capturable.
// ---------------------------------------------------------------------------
extern "C" void kernel_launch(void* const* d_in, const int* in_sizes, int n_in,
                              void* d_out, int out_size)
{
    const float* x      = (const float*)d_in[0];
    const float* W_ih0  = (const float*)d_in[1];
    const float* W_hh0  = (const float*)d_in[2];
    const float* b_ih0  = (const float*)d_in[3];
    const float* b_hh0  = (const float*)d_in[4];
    const float* W_ih1  = (const float*)d_in[5];
    const float* W_hh1  = (const float*)d_in[6];
    const float* b_ih1  = (const float*)d_in[7];
    const float* b_hh1  = (const float*)d_in[8];
    const float* Wq     = (const float*)d_in[9];
    const float* bq     = (const float*)d_in[10];
    const float* Wk     = (const float*)d_in[11];
    const float* bk     = (const float*)d_in[12];
    const float* Wv     = (const float*)d_in[13];
    const float* bv     = (const float*)d_in[14];
    const float* R      = (const float*)d_in[15];
    const float* W_gate = (const float*)d_in[16];
    const float* b_gate = (const float*)d_in[17];
    const float* W1     = (const float*)d_in[18];
    const float* b1     = (const float*)d_in[19];
    const float* W2     = (const float*)d_in[20];
    const float* b2     = (const float*)d_in[21];
    float* out = (float*)d_out;

    float *xw, *ys0, *S, *wt_ih0, *wt_hh0, *wt_ih1, *wt_hh1, *wt_w1;
    float *qh1, *kh1, *vh1, *Bb, *qh2, *kh2, *vh2, *Sp, *Smix, *mlp, *yraw;
    cudaGetSymbolAddress((void**)&xw, g_xw);
    cudaGetSymbolAddress((void**)&ys0, g_ys0);
    cudaGetSymbolAddress((void**)&S, g_S);
    cudaGetSymbolAddress((void**)&wt_ih0, g_wt_ih0);
    cudaGetSymbolAddress((void**)&wt_hh0, g_wt_hh0);
    cudaGetSymbolAddress((void**)&wt_ih1, g_wt_ih1);
    cudaGetSymbolAddress((void**)&wt_hh1, g_wt_hh1);
    cudaGetSymbolAddress((void**)&wt_w1, g_wt_w1);
    cudaGetSymbolAddress((void**)&qh1, g_qh1);
    cudaGetSymbolAddress((void**)&kh1, g_kh1);
    cudaGetSymbolAddress((void**)&vh1, g_vh1);
    cudaGetSymbolAddress((void**)&Bb, g_B);
    cudaGetSymbolAddress((void**)&qh2, g_qh2);
    cudaGetSymbolAddress((void**)&kh2, g_kh2);
    cudaGetSymbolAddress((void**)&vh2, g_vh2);
    cudaGetSymbolAddress((void**)&Sp, g_Sp);
    cudaGetSymbolAddress((void**)&Smix, g_Smix);
    cudaGetSymbolAddress((void**)&mlp, g_mlp);
    cudaGetSymbolAddress((void**)&yraw, g_yraw);

    cudaFuncSetAttribute(gru_rec_kernel,
                         cudaFuncAttributeMaxDynamicSharedMemorySize, REC_SMEM);

    const dim3 blk2(16, 16);
    const dim3 tb(32, 8);

    // ---- weight transposes (tiny) ----
    transpose_kernel<<<dim3(INDIM / 32, G3 / 32), tb>>>(W_ih0, wt_ih0, G3, INDIM);
    transpose_kernel<<<dim3(HH / 32, G3 / 32), tb>>>(W_hh0, wt_hh0, G3, HH);
    transpose_kernel<<<dim3(HH / 32, G3 / 32), tb>>>(W_ih1, wt_ih1, G3, HH);
    transpose_kernel<<<dim3(HH / 32, G3 / 32), tb>>>(W_hh1, wt_hh1, G3, HH);
    transpose_kernel<<<dim3(HH / 32, HH / 32), tb>>>(W1, wt_w1, HH, HH);

    // ---- Layer 0 ----
    gemm2_kernel<<<dim3(G3 / 128, NTROWS / 128), 256>>>(
        x, wt_ih0, b_ih0, xw, NTROWS, G3, INDIM);
    gru_rec_kernel<<<NB / RBM, RTHREADS, REC_SMEM>>>(
        wt_hh0, b_hh0, xw, ys0, nullptr);

    // ---- Layer 1 ----
    gemm2_kernel<<<dim3(G3 / 128, NTROWS / 128), 256>>>(
        ys0, wt_ih1, b_ih1, xw, NTROWS, G3, HH);
    gru_rec_kernel<<<NB / RBM, RTHREADS, REC_SMEM>>>(
        wt_hh1, b_hh1, xw, nullptr, S);

    // ---- Attention: B = MHA(R, S, S), S' = MHA(S, B, B) ----
    proj_kernel<<<dim3(8, 2, NHD), blk2>>>(R, CC, Wq, bq, qh1);
    proj_kernel<<<dim3(8, NB / 16, NHD), blk2>>>(S, NB, Wk, bk, kh1);
    proj_kernel<<<dim3(8, NB / 16, NHD), blk2>>>(S, NB, Wv, bv, vh1);
    attn1_kernel<<<NHD * CC, 256>>>(qh1, kh1, vh1, Bb);
    proj_kernel<<<dim3(8, NB / 16, NHD), blk2>>>(S, NB, Wq, bq, qh2);
    proj_kernel<<<dim3(8, 2, NHD), blk2>>>(Bb, CC, Wk, bk, kh2);
    proj_kernel<<<dim3(8, 2, NHD), blk2>>>(Bb, CC, Wv, bv, vh2);
    attn2_kernel<<<dim3(NB, NHD), 128>>>(qh2, kh2, vh2, Sp);

    // ---- Gate mix + MLP + output ----
    gate_mix_kernel<<<NB, 256>>>(S, Sp, W_gate, b_gate, Smix);
    gemm2_kernel<<<dim3(HH / 128, NB / 128), 256>>>(
        Smix, wt_w1, b1, mlp, NB, HH, HH);
    relu_add_kernel<<<(NB * HH) / 256, 256>>>(mlp, Smix);
    rowdot_kernel<<<NB, 256>>>(Smix, W2, b2, yraw);
    normalize_kernel<<<1, 1024>>>(yraw, out);
}